// round 6
// baseline (speedup 1.0000x reference)
#include <cuda_runtime.h>

#define NN 8192
#define TPB 256
#define NWARP (TPB / 32)
#define KW (NN / 4 / 32)      // 64 float4 per lane per row
#define EPS 1e-5f

// ---------------- device scratch ----------------
__device__ float g_stats[12];   // 6 BN stages x (sum, sumsq)
__device__ __align__(16) float g_y1[NN], g_y2[NN];
__device__ __align__(16) float g_gg1[NN], g_gg2[NN];
__device__ __align__(16) float g_z1[NN], g_z2[NN];
__device__ __align__(16) float g_f0[NN], g_f1[NN];
__device__ __align__(16) float g_u0[NN], g_u1[NN];
__device__ __align__(16) float g_g3[NN], g_z3[NN];

__global__ void zero_stats_kernel() {
    if (threadIdx.x < 12) g_stats[threadIdx.x] = 0.f;
}

__device__ __forceinline__ float2 bn_coeffs(int slot, float cnt, float ga, float be) {
    float m = g_stats[2 * slot] / cnt;
    float v = g_stats[2 * slot + 1] / cnt - m * m;
    float scale = ga * rsqrtf(v + EPS);
    return make_float2(scale, be - m * scale);   // f = h*scale + shift
}

// block stats flush
__device__ __forceinline__ void flush_stats(float s, float s2, float (*sred)[2],
                                            int lane, int wid, int tid, float* dst) {
    if (lane == 0) { sred[wid][0] = s; sred[wid][1] = s2; }
    __syncthreads();
    if (tid == 0) {
        float a = 0.f, b = 0.f;
#pragma unroll
        for (int i = 0; i < NWARP; i++) { a += sred[i][0]; b += sred[i][1]; }
        atomicAdd(dst, a);
        atomicAdd(dst + 1, b);
    }
}

// warp row dot: A bypasses L1 (.cg first read / .cs dead read), x via L1 (__ldg)
template <bool STREAM>
__device__ __forceinline__ float warp_row_dot(const float* __restrict__ A, int row,
                                              const float4* __restrict__ x4, int lane) {
    const float4* a4 = (const float4*)(A + (size_t)row * NN);
    float acc0 = 0.f, acc1 = 0.f, acc2 = 0.f, acc3 = 0.f;
#pragma unroll
    for (int k = 0; k < KW; k += 4) {
        float4 a0 = STREAM ? __ldcs(a4 + lane + (k + 0) * 32) : __ldcg(a4 + lane + (k + 0) * 32);
        float4 a1 = STREAM ? __ldcs(a4 + lane + (k + 1) * 32) : __ldcg(a4 + lane + (k + 1) * 32);
        float4 a2 = STREAM ? __ldcs(a4 + lane + (k + 2) * 32) : __ldcg(a4 + lane + (k + 2) * 32);
        float4 a3 = STREAM ? __ldcs(a4 + lane + (k + 3) * 32) : __ldcg(a4 + lane + (k + 3) * 32);
        float4 x0 = __ldg(x4 + lane + (k + 0) * 32);
        float4 x1 = __ldg(x4 + lane + (k + 1) * 32);
        float4 x2 = __ldg(x4 + lane + (k + 2) * 32);
        float4 x3 = __ldg(x4 + lane + (k + 3) * 32);
        acc0 = fmaf(a0.x, x0.x, acc0); acc0 = fmaf(a0.y, x0.y, acc0);
        acc0 = fmaf(a0.z, x0.z, acc0); acc0 = fmaf(a0.w, x0.w, acc0);
        acc1 = fmaf(a1.x, x1.x, acc1); acc1 = fmaf(a1.y, x1.y, acc1);
        acc1 = fmaf(a1.z, x1.z, acc1); acc1 = fmaf(a1.w, x1.w, acc1);
        acc2 = fmaf(a2.x, x2.x, acc2); acc2 = fmaf(a2.y, x2.y, acc2);
        acc2 = fmaf(a2.z, x2.z, acc2); acc2 = fmaf(a2.w, x2.w, acc2);
        acc3 = fmaf(a3.x, x3.x, acc3); acc3 = fmaf(a3.y, x3.y, acc3);
        acc3 = fmaf(a3.z, x3.z, acc3); acc3 = fmaf(a3.w, x3.w, acc3);
    }
    float acc = (acc0 + acc1) + (acc2 + acc3);
#pragma unroll
    for (int o = 16; o > 0; o >>= 1) acc += __shfl_xor_sync(0xffffffffu, acc, o);
    return acc;
}

// ---- pass 1 (dual): y = A @ F ; stats over relu(y*w+b) [N,4] -> slot z
__global__ __launch_bounds__(TPB) void mv1(
    const float* __restrict__ Aa, const float* __restrict__ Ab,
    const float* __restrict__ x,
    const float* __restrict__ w11, const float* __restrict__ b11,
    const float* __restrict__ w21, const float* __restrict__ b21)
{
    __shared__ float sred[NWARP][2];
    int z = blockIdx.z;
    const float* A  = z ? Ab : Aa;
    const float4* x4 = (const float4*)(x + z * NN);
    float*       yp = z ? g_y2 : g_y1;
    const float* w  = z ? w21 : w11;
    const float* b  = z ? b21 : b11;
    int tid = threadIdx.x, lane = tid & 31, wid = tid >> 5;

    int row = blockIdx.x * NWARP + wid;
    float t = warp_row_dot<false>(A, row, x4, lane);

    float s = 0.f, s2 = 0.f;
    if (lane == 0) {
        yp[row] = t;
        float v0 = fmaxf(fmaf(t, w[0], b[0]), 0.f), v1 = fmaxf(fmaf(t, w[1], b[1]), 0.f);
        float v2 = fmaxf(fmaf(t, w[2], b[2]), 0.f), v3 = fmaxf(fmaf(t, w[3], b[3]), 0.f);
        s  = v0 + v1 + v2 + v3;
        s2 = v0 * v0 + v1 * v1 + v2 * v2 + v3 * v3;
    }
    flush_stats(s, s2, sred, lane, wid, tid, &g_stats[2 * z]);
}

// ---- transform: g1,g2 from y1,y2 (BN slots 0,1)
__global__ void t2_kernel(
    const float* __restrict__ w11, const float* __restrict__ b11, const float* __restrict__ w12,
    const float* __restrict__ w21, const float* __restrict__ b21, const float* __restrict__ w22,
    const float* __restrict__ gamma, const float* __restrict__ beta)
{
    float ga = gamma[0], be = beta[0];
    float2 c0 = bn_coeffs(0, (float)(NN * 4), ga, be);
    float2 c1 = bn_coeffs(1, (float)(NN * 4), ga, be);
    int j = blockIdx.x * blockDim.x + threadIdx.x;
    if (j >= NN) return;
    {
        float yy = g_y1[j];
        float h0 = fmaxf(fmaf(yy, w11[0], b11[0]), 0.f);
        float h1 = fmaxf(fmaf(yy, w11[1], b11[1]), 0.f);
        float h2 = fmaxf(fmaf(yy, w11[2], b11[2]), 0.f);
        float h3 = fmaxf(fmaf(yy, w11[3], b11[3]), 0.f);
        g_gg1[j] = w12[0] * fmaf(h0, c0.x, c0.y) + w12[1] * fmaf(h1, c0.x, c0.y)
                 + w12[2] * fmaf(h2, c0.x, c0.y) + w12[3] * fmaf(h3, c0.x, c0.y);
    }
    {
        float yy = g_y2[j];
        float h0 = fmaxf(fmaf(yy, w21[0], b21[0]), 0.f);
        float h1 = fmaxf(fmaf(yy, w21[1], b21[1]), 0.f);
        float h2 = fmaxf(fmaf(yy, w21[2], b21[2]), 0.f);
        float h3 = fmaxf(fmaf(yy, w21[3], b21[3]), 0.f);
        g_gg2[j] = w22[0] * fmaf(h0, c1.x, c1.y) + w22[1] * fmaf(h1, c1.x, c1.y)
                 + w22[2] * fmaf(h2, c1.x, c1.y) + w22[3] * fmaf(h3, c1.x, c1.y);
    }
}

// ---- pass 2 (dual): z = A @ g reversed ; stats over relu(z+b) -> slot 2+z
__global__ __launch_bounds__(TPB) void mv2(
    const float* __restrict__ Aa, const float* __restrict__ Ab,
    const float* __restrict__ b12, const float* __restrict__ b22)
{
    __shared__ float sred[NWARP][2];
    int z = blockIdx.z;
    const float* A = z ? Ab : Aa;
    const float4* x4 = (const float4*)(z ? g_gg2 : g_gg1);
    float* zp = z ? g_z2 : g_z1;
    float bb = z ? b22[0] : b12[0];
    int tid = threadIdx.x, lane = tid & 31, wid = tid >> 5;

    int row = NN - 1 - (blockIdx.x * NWARP + wid);   // reverse: L2 tail reuse
    float t = warp_row_dot<true>(A, row, x4, lane);

    float s = 0.f, s2 = 0.f;
    if (lane == 0) {
        zp[row] = t;
        float v = fmaxf(t + bb, 0.f);
        s = v; s2 = v * v;
    }
    flush_stats(s, s2, sred, lane, wid, tid, &g_stats[2 * (2 + z)]);
}

// ---- transform: f0,f1 from z1,z2 (BN slots 2,3)
__global__ void t3_kernel(
    const float* __restrict__ b12, const float* __restrict__ b22,
    const float* __restrict__ gamma, const float* __restrict__ beta)
{
    float ga = gamma[0], be = beta[0];
    float2 c2 = bn_coeffs(2, (float)NN, ga, be);
    float2 c3 = bn_coeffs(3, (float)NN, ga, be);
    float bb1 = b12[0], bb2 = b22[0];
    int j = blockIdx.x * blockDim.x + threadIdx.x;
    if (j >= NN) return;
    g_f0[j] = fmaxf(fmaf(fmaxf(g_z1[j] + bb1, 0.f), c2.x, c2.y), 0.f);
    g_f1[j] = fmaxf(fmaf(fmaxf(g_z2[j] + bb2, 0.f), c3.x, c3.y), 0.f);
}

// ---- pass 3: (u0,u1) = A12 @ [f0 f1] ; stats of concat activations -> slot 4
__global__ __launch_bounds__(TPB) void mv3(
    const float* __restrict__ A,
    const float* __restrict__ wc1, const float* __restrict__ bc1)
{
    __shared__ float sred[NWARP][2];
    int tid = threadIdx.x, lane = tid & 31, wid = tid >> 5;
    const float4* f04 = (const float4*)g_f0;
    const float4* f14 = (const float4*)g_f1;

    int row = blockIdx.x * NWARP + wid;
    const float4* a4 = (const float4*)(A + (size_t)row * NN);
    float p00 = 0.f, p01 = 0.f, p10 = 0.f, p11 = 0.f;
#pragma unroll
    for (int k = 0; k < KW; k += 2) {
        float4 a0 = __ldcg(a4 + lane + (k + 0) * 32);
        float4 a1 = __ldcg(a4 + lane + (k + 1) * 32);
        float4 u0 = __ldg(f04 + lane + (k + 0) * 32);
        float4 u1 = __ldg(f04 + lane + (k + 1) * 32);
        float4 v0 = __ldg(f14 + lane + (k + 0) * 32);
        float4 v1 = __ldg(f14 + lane + (k + 1) * 32);
        p00 = fmaf(a0.x, u0.x, p00); p00 = fmaf(a0.y, u0.y, p00);
        p00 = fmaf(a0.z, u0.z, p00); p00 = fmaf(a0.w, u0.w, p00);
        p01 = fmaf(a1.x, u1.x, p01); p01 = fmaf(a1.y, u1.y, p01);
        p01 = fmaf(a1.z, u1.z, p01); p01 = fmaf(a1.w, u1.w, p01);
        p10 = fmaf(a0.x, v0.x, p10); p10 = fmaf(a0.y, v0.y, p10);
        p10 = fmaf(a0.z, v0.z, p10); p10 = fmaf(a0.w, v0.w, p10);
        p11 = fmaf(a1.x, v1.x, p11); p11 = fmaf(a1.y, v1.y, p11);
        p11 = fmaf(a1.z, v1.z, p11); p11 = fmaf(a1.w, v1.w, p11);
    }
    float t0 = p00 + p01, t1 = p10 + p11;
#pragma unroll
    for (int o = 16; o > 0; o >>= 1) {
        t0 += __shfl_xor_sync(0xffffffffu, t0, o);
        t1 += __shfl_xor_sync(0xffffffffu, t1, o);
    }

    float s = 0.f, s2 = 0.f;
    if (lane == 0) {
        g_u0[row] = t0;
        g_u1[row] = t1;
        float v0 = fmaxf(t0 * wc1[0] + t1 * wc1[4] + bc1[0], 0.f);
        float v1 = fmaxf(t0 * wc1[1] + t1 * wc1[5] + bc1[1], 0.f);
        float v2 = fmaxf(t0 * wc1[2] + t1 * wc1[6] + bc1[2], 0.f);
        float v3 = fmaxf(t0 * wc1[3] + t1 * wc1[7] + bc1[3], 0.f);
        s  = v0 + v1 + v2 + v3;
        s2 = v0 * v0 + v1 * v1 + v2 * v2 + v3 * v3;
    }
    flush_stats(s, s2, sred, lane, wid, tid, &g_stats[8]);
}

// ---- transform: g3 from u0,u1 (BN slot 4)
__global__ void t4_kernel(
    const float* __restrict__ wc1, const float* __restrict__ bc1,
    const float* __restrict__ wc2,
    const float* __restrict__ gamma, const float* __restrict__ beta)
{
    float2 c = bn_coeffs(4, (float)(NN * 4), gamma[0], beta[0]);
    int j = blockIdx.x * blockDim.x + threadIdx.x;
    if (j >= NN) return;
    float t0 = g_u0[j], t1 = g_u1[j];
    float h0 = fmaxf(t0 * wc1[0] + t1 * wc1[4] + bc1[0], 0.f);
    float h1 = fmaxf(t0 * wc1[1] + t1 * wc1[5] + bc1[1], 0.f);
    float h2 = fmaxf(t0 * wc1[2] + t1 * wc1[6] + bc1[2], 0.f);
    float h3 = fmaxf(t0 * wc1[3] + t1 * wc1[7] + bc1[3], 0.f);
    g_g3[j] = wc2[0] * fmaf(h0, c.x, c.y) + wc2[1] * fmaf(h1, c.x, c.y)
            + wc2[2] * fmaf(h2, c.x, c.y) + wc2[3] * fmaf(h3, c.x, c.y);
}

// ---- pass 4: z3 = A12 @ g3 reversed ; stats relu(z3+bc2) -> slot 5
__global__ __launch_bounds__(TPB) void mv4(
    const float* __restrict__ A, const float* __restrict__ bc2)
{
    __shared__ float sred[NWARP][2];
    float bb = bc2[0];
    int tid = threadIdx.x, lane = tid & 31, wid = tid >> 5;
    const float4* x4 = (const float4*)g_g3;

    int row = NN - 1 - (blockIdx.x * NWARP + wid);
    float t = warp_row_dot<true>(A, row, x4, lane);

    float s = 0.f, s2 = 0.f;
    if (lane == 0) {
        g_z3[row] = t;
        float v = fmaxf(t + bb, 0.f);
        s = v; s2 = v * v;
    }
    flush_stats(s, s2, sred, lane, wid, tid, &g_stats[10]);
}

// ---- final: out = relu(BN(relu(z3 + bc2))) with slot 5
__global__ void final_kernel(const float* __restrict__ bc2,
                             const float* __restrict__ gamma, const float* __restrict__ beta,
                             float* __restrict__ out)
{
    float2 c = bn_coeffs(5, (float)NN, gamma[0], beta[0]);
    float bb = bc2[0];
    int j = blockIdx.x * blockDim.x + threadIdx.x;
    if (j >= NN) return;
    float h = fmaxf(g_z3[j] + bb, 0.f);
    out[j] = fmaxf(fmaf(h, c.x, c.y), 0.f);
}

// ---------------- launch ----------------
extern "C" void kernel_launch(void* const* d_in, const int* in_sizes, int n_in,
                              void* d_out, int out_size)
{
    const float* x     = (const float*)d_in[0];
    const float* adj   = (const float*)d_in[1];
    const float* w11   = (const float*)d_in[2];
    const float* b11   = (const float*)d_in[3];
    const float* w12   = (const float*)d_in[4];
    const float* b12   = (const float*)d_in[5];
    const float* w21   = (const float*)d_in[6];
    const float* b21   = (const float*)d_in[7];
    const float* w22   = (const float*)d_in[8];
    const float* b22   = (const float*)d_in[9];
    const float* wc1   = (const float*)d_in[10];
    const float* bc1   = (const float*)d_in[11];
    const float* wc2   = (const float*)d_in[12];
    const float* bc2   = (const float*)d_in[13];
    const float* gamma = (const float*)d_in[14];
    const float* beta  = (const float*)d_in[15];
    float* out = (float*)d_out;

    const float* A1  = adj;
    const float* A2  = adj + (size_t)NN * NN;
    const float* A12 = adj + 2 * (size_t)NN * NN;

    dim3 g2(NN / NWARP, 1, 2);   // 1024 x-blocks per matrix, dual
    dim3 g1(NN / NWARP, 1, 1);
    const int TB = 256, GB = NN / 256;

    zero_stats_kernel<<<1, 32>>>();
    mv1<<<g2, TPB>>>(A1, A2, x, w11, b11, w21, b21);
    t2_kernel<<<GB, TB>>>(w11, b11, w12, w21, b21, w22, gamma, beta);
    mv2<<<g2, TPB>>>(A1, A2, b12, b22);
    t3_kernel<<<GB, TB>>>(b12, b22, gamma, beta);
    mv3<<<g1, TPB>>>(A12, wc1, bc1);
    t4_kernel<<<GB, TB>>>(wc1, bc1, wc2, gamma, beta);
    mv4<<<g1, TPB>>>(A12, bc2);
    final_kernel<<<GB, TB>>>(bc2, gamma, beta, out);

    (void)in_sizes; (void)n_in; (void)out_size;
}